// round 16
// baseline (speedup 1.0000x reference)
#include <cuda_runtime.h>
#include <cuda_fp16.h>
#include <stdint.h>

// ---------------- problem constants ----------------
#define BB 8
#define CC 128
#define HH 256
#define WW 256
#define OO 128
#define HWSZ (HH * WW)
#define NTHREADS 512

// A/B smem rows: 64 h2-words padded to 72
#define RWRD 72

// ---------------- smem layout (bytes) ----------------
#define SM_A   0                             // A: 128 x RWRD uint32 (36864 B); rows 0-63 reused as fp16 epilogue bounce
#define SM_B   (128 * RWRD * 4)              // B: 128 x RWRD uint32 (36864 B)
#define SM_W   (SM_B + 128 * RWRD * 4)       // row-masked weights float4[128]
#define SM_O   (SM_W + 2048)                 // int4 per channel {off0, off1, ifx, -}
#define SM_TOTAL (SM_O + 2048)               // 77824 B -> 2 CTAs/SM

// ---------------- precomputed globals (written by prep kernel) ----------------
__device__ float4   g_PW[CC];
__device__ int2     g_PI[CC];
__device__ uint32_t g_Bw[OO * 64];           // fp16x2 w_pw, pair-interleaved words

// pair-interleave: logical words w and w+4 land at adjacent positions
__host__ __device__ __forceinline__ int pairpos(int w) {
    return (w & ~7) + ((w & 3) << 1) + ((w >> 2) & 1);
}

__device__ __forceinline__ uint32_t packh2(float lo, float hi) {
    __half2 h = __floats2half2_rn(lo, hi);
    return *(uint32_t*)&h;
}

__device__ __forceinline__ void mma16(float* d, uint32_t a0, uint32_t a1, uint32_t a2,
                                      uint32_t a3, uint32_t b0, uint32_t b1) {
    asm volatile(
        "mma.sync.aligned.m16n8k16.row.col.f32.f16.f16.f32 "
        "{%0,%1,%2,%3}, {%4,%5,%6,%7}, {%8,%9}, {%0,%1,%2,%3};"
        : "+f"(d[0]), "+f"(d[1]), "+f"(d[2]), "+f"(d[3])
        : "r"(a0), "r"(a1), "r"(a2), "r"(a3), "r"(b0), "r"(b1));
}

// ---------------- prep kernel: params + fp16 pre-layout of w_pw ----------------
__global__ void prep_kernel(const float* __restrict__ theta, const float* __restrict__ wdw,
                            const float* __restrict__ wpw) {
    int t = blockIdx.x * blockDim.x + threadIdx.x;
    if (t < CC) {
        float ty = -theta[2 * t];
        float tx = -theta[2 * t + 1];
        float fy = floorf(ty), fx = floorf(tx);
        float dy = ty - fy, dx = tx - fx;
        float wd = wdw[t];
        g_PI[t] = make_int2((int)fy, (int)fx);
        g_PW[t] = make_float4((1.0f - dy) * (1.0f - dx) * wd,
                              (1.0f - dy) * dx * wd,
                              dy * (1.0f - dx) * wd,
                              dy * dx * wd);
    }
    if (t < OO * CC / 4) {                 // 4096 float4 chunks
        int o = t >> 5;
        int c4 = (t & 31) << 2;
        float4 v = ((const float4*)wpw)[t];
        int p0 = pairpos(c4 >> 1);
        g_Bw[o * 64 + p0]     = packh2(v.x, v.y);
        g_Bw[o * 64 + p0 + 2] = packh2(v.z, v.w);
    }
}

// ---------------- gather: both subtiles, one pass ----------------
// LO0=true:  subtile0 (cols j0a+p)      needs low-edge column guards, subtile1 interior
// LO0=false: subtile1 (cols j0a+64+p)   needs high-edge column guards, subtile0 interior
template<bool LO0>
__device__ __forceinline__ void gather_both(
    const float* __restrict__ xb, uint32_t* __restrict__ Asw,
    const float4* __restrict__ SW, const int4* __restrict__ SO,
    int p, int cs, int j0a)
{
    const int jj = cs & 3;
    const int g0 = (cs >> 2) << 2;
    const int sg = ((p >> 2) & 7) << 1;
    const int jA = j0a + p;
    const int jB = jA + 64;
    uint32_t* A0 = Asw + p * RWRD;
    uint32_t* A1 = Asw + (64 + p) * RWRD;

    #pragma unroll
    for (int q = 0; q < 4; q++) {
        const int g = g0 + q;
        const int c00 = 16 * g + 2 * jj;
        float sA[4], sB[4];
        #pragma unroll
        for (int cc = 0; cc < 4; cc++) {
            int c = c00 + (cc & 1) + ((cc & 2) ? 8 : 0);
            int4 off = SO[c];
            float4 wv = SW[c];
            const float* b0 = xb + off.x;
            const float* b1 = xb + off.y;
            float a00, a01, a10, a11;
            float c00v, c01v, c10v, c11v;
            if (LO0) {
                int qq = jA + off.z;
                bool ok0 = qq >= 0, ok1 = qq >= -1;
                a00 = ok0 ? b0[jA] : 0.0f;  a01 = ok1 ? b0[jA + 1] : 0.0f;
                a10 = ok0 ? b1[jA] : 0.0f;  a11 = ok1 ? b1[jA + 1] : 0.0f;
                c00v = b0[jB]; c01v = b0[jB + 1]; c10v = b1[jB]; c11v = b1[jB + 1];
            } else {
                a00 = b0[jA]; a01 = b0[jA + 1]; a10 = b1[jA]; a11 = b1[jA + 1];
                int qq = jB + off.z;
                bool ok0 = qq <= 255, ok1 = qq <= 254;
                c00v = ok0 ? b0[jB] : 0.0f;  c01v = ok1 ? b0[jB + 1] : 0.0f;
                c10v = ok0 ? b1[jB] : 0.0f;  c11v = ok1 ? b1[jB + 1] : 0.0f;
            }
            sA[cc] = a00 * wv.x + a01 * wv.y + a10 * wv.z + a11 * wv.w;
            sB[cc] = c00v * wv.x + c01v * wv.y + c10v * wv.z + c11v * wv.w;
        }
        const int pos = (8 * g + 2 * jj) ^ sg;
        *(uint2*)(A0 + pos) = make_uint2(packh2(sA[0], sA[1]), packh2(sA[2], sA[3]));
        *(uint2*)(A1 + pos) = make_uint2(packh2(sB[0], sB[1]), packh2(sB[2], sB[3]));
    }
}

// ---------------- main kernel ----------------
__global__ void __launch_bounds__(NTHREADS, 2)
as2d_kernel(const float* __restrict__ x, float* __restrict__ out) {
    extern __shared__ char smem[];
    const int tid = threadIdx.x;
    const int wid = tid >> 5;
    const int lid = tid & 31;
    const int gid = lid >> 2;
    const int tig = lid & 3;

    // pair tiles: 512 pairs per batch (256 rows x 2 half-rows of 128 px = 2 subtiles)
    const int blk = blockIdx.x;
    const int b = blk >> 9;
    const int rem = blk & 511;
    const int row = rem >> 1;
    const int pairid = rem & 1;
    const int j0a = pairid << 7;

    uint32_t* Asw = (uint32_t*)(smem + SM_A);
    uint32_t* Bsw = (uint32_t*)(smem + SM_B);
    float4*   SW  = (float4*)(smem + SM_W);
    int4*     SO  = (int4*)(smem + SM_O);

    // ---- per-CTA setup: row validity folded into weights, c*HWSZ folded into offsets ----
    if (tid < CC) {
        int2 iv = g_PI[tid];
        float4 w = g_PW[tid];
        int r0 = row + iv.x;
        int r1 = r0 + 1;
        bool rok0 = (unsigned)r0 < (unsigned)HH;
        bool rok1 = (unsigned)r1 < (unsigned)HH;
        int cr0 = min(max(r0, 0), HH - 1);
        int cr1 = min(max(r1, 0), HH - 1);
        SW[tid] = make_float4(rok0 ? w.x : 0.0f, rok0 ? w.y : 0.0f,
                              rok1 ? w.z : 0.0f, rok1 ? w.w : 0.0f);
        SO[tid] = make_int4(tid * HWSZ + cr0 * WW + iv.y,
                            tid * HWSZ + cr1 * WW + iv.y, iv.y, 0);
    }
    // ---- stage B tile (once per pair) ----
    #pragma unroll
    for (int i = 0; i < 4; i++) {
        int w4 = tid + i * NTHREADS;
        int r = w4 >> 4;
        int pos = (w4 & 15) << 2;
        uint4 v = ((const uint4*)g_Bw)[w4];
        *(uint4*)(Bsw + r * RWRD + pos) = v;
    }
    __syncthreads();

    // ---- gather both subtiles ----
    {
        const int p = tid & 63;
        const int cs = tid >> 6;
        const float* xb = x + (size_t)b * CC * HWSZ;
        if (pairid == 0)
            gather_both<true>(xb, Asw, SW, SO, p, cs, j0a);
        else
            gather_both<false>(xb, Asw, SW, SO, p, cs, j0a);
    }
    __syncthreads();

    // ---- two subtile GEMMs + epilogues ----
    const int wm = wid & 3;
    const int wn = wid >> 2;
    #pragma unroll
    for (int t = 0; t < 2; t++) {
        float d[4][4] = {};
        {
            const uint32_t* At = Asw + t * 64 * RWRD;
            const int r1 = wm * 16 + gid;
            const int r2 = r1 + 8;
            const int sg1 = ((r1 >> 2) & 7) << 1;
            const int sg2 = ((r2 >> 2) & 7) << 1;
            const uint32_t* A1 = At + r1 * RWRD;
            const uint32_t* A2 = At + r2 * RWRD;
            const uint32_t* Bb = Bsw + (wn * 32 + gid) * RWRD + 2 * tig;
            #pragma unroll
            for (int k = 0; k < 8; k++) {
                int t2 = 8 * k + 2 * tig;
                uint2 aA = *(const uint2*)(A1 + (t2 ^ sg1));
                uint2 aB = *(const uint2*)(A2 + (t2 ^ sg2));
                #pragma unroll
                for (int nt = 0; nt < 4; nt++) {
                    uint2 bv = *(const uint2*)(Bb + nt * 8 * RWRD + 8 * k);
                    mma16(d[nt], aA.x, aB.x, aA.y, aB.y, bv.x, bv.y);
                }
            }
        }
        __syncthreads();   // all warps done reading A rows 0-63 (t=0) / E2 free (t=1)

        // ---- epilogue STS: fp16 pairs along o into E2 (= A rows 0-63 region) ----
        {
            const int pb = wm * 16 + gid;
            #pragma unroll
            for (int nt = 0; nt < 4; nt++) {
                int o2 = wn * 16 + nt * 4 + tig;     // o-pair index (o = 2*o2, 2*o2+1)
                Asw[o2 * RWRD + pb]     = packh2(d[nt][0], d[nt][1]);
                Asw[o2 * RWRD + pb + 8] = packh2(d[nt][2], d[nt][3]);
            }
        }
        __syncthreads();

        // ---- epilogue out: each thread expands one o-pair x 4 px -> 2 coalesced STG.128 ----
        {
            const int o2a = tid >> 4;
            const int l4 = tid & 15;
            float* obase = out + (size_t)b * OO * HWSZ + (size_t)row * WW + j0a + t * 64 + 4 * l4;
            #pragma unroll
            for (int s2 = 0; s2 < 2; s2++) {
                int o2 = o2a + s2 * 32;
                uint4 v4 = *(const uint4*)(Asw + o2 * RWRD + 4 * l4);
                float2 f0 = __half22float2(*(__half2*)&v4.x);
                float2 f1 = __half22float2(*(__half2*)&v4.y);
                float2 f2 = __half22float2(*(__half2*)&v4.z);
                float2 f3 = __half22float2(*(__half2*)&v4.w);
                *(float4*)(obase + (size_t)(2 * o2) * HWSZ) =
                    make_float4(f0.x, f1.x, f2.x, f3.x);
                *(float4*)(obase + (size_t)(2 * o2 + 1) * HWSZ) =
                    make_float4(f0.y, f1.y, f2.y, f3.y);
            }
        }
        // no sync needed: next mainloop reads A rows 64-127 / B only;
        // its post-mainloop sync orders E2 reuse against these reads.
    }
}

extern "C" void kernel_launch(void* const* d_in, const int* in_sizes, int n_in,
                              void* d_out, int out_size) {
    (void)in_sizes; (void)n_in; (void)out_size;
    const float* x     = (const float*)d_in[0];
    const float* theta = (const float*)d_in[1];
    const float* wdw   = (const float*)d_in[2];
    const float* wpw   = (const float*)d_in[3];
    float* out = (float*)d_out;

    prep_kernel<<<8, 512>>>(theta, wdw, wpw);
    cudaFuncSetAttribute(as2d_kernel, cudaFuncAttributeMaxDynamicSharedMemorySize, SM_TOTAL);
    as2d_kernel<<<BB * (HH * WW / 128), NTHREADS, SM_TOTAL>>>(x, out);
}

// round 17
// speedup vs baseline: 1.0158x; 1.0158x over previous
#include <cuda_runtime.h>
#include <cuda_fp16.h>
#include <stdint.h>

// ---------------- problem constants ----------------
#define BB 8
#define CC 128
#define HH 256
#define WW 256
#define OO 128
#define HWSZ (HH * WW)
#define NTHREADS 512

// A/B smem rows: 64 h2-words padded to 72
#define RWRD 72

// ---------------- smem layout (bytes) ----------------
#define SM_A   0                             // A: 128 x RWRD uint32 (36864 B); rows 0-63 reused as fp16 epilogue bounce
#define SM_B   (128 * RWRD * 4)              // B: 128 x RWRD uint32 (36864 B)
#define SM_W   (SM_B + 128 * RWRD * 4)       // row-masked weights float4[128]
#define SM_O   (SM_W + 2048)                 // int4 per channel {off0, off1, ifx, -}
#define SM_TOTAL (SM_O + 2048)               // 77824 B -> 2 CTAs/SM

// ---------------- precomputed globals (written by prep kernel) ----------------
__device__ float4   g_PW[CC];
__device__ int2     g_PI[CC];
__device__ uint32_t g_Bw[OO * 64];           // fp16x2 w_pw, pair-interleaved words

// pair-interleave: logical words w and w+4 land at adjacent positions
__host__ __device__ __forceinline__ int pairpos(int w) {
    return (w & ~7) + ((w & 3) << 1) + ((w >> 2) & 1);
}

__device__ __forceinline__ uint32_t packh2(float lo, float hi) {
    __half2 h = __floats2half2_rn(lo, hi);
    return *(uint32_t*)&h;
}

__device__ __forceinline__ void mma16(float* d, uint32_t a0, uint32_t a1, uint32_t a2,
                                      uint32_t a3, uint32_t b0, uint32_t b1) {
    asm volatile(
        "mma.sync.aligned.m16n8k16.row.col.f32.f16.f16.f32 "
        "{%0,%1,%2,%3}, {%4,%5,%6,%7}, {%8,%9}, {%0,%1,%2,%3};"
        : "+f"(d[0]), "+f"(d[1]), "+f"(d[2]), "+f"(d[3])
        : "r"(a0), "r"(a1), "r"(a2), "r"(a3), "r"(b0), "r"(b1));
}

// ---------------- prep kernel: params + fp16 pre-layout of w_pw ----------------
__global__ void prep_kernel(const float* __restrict__ theta, const float* __restrict__ wdw,
                            const float* __restrict__ wpw) {
    int t = blockIdx.x * blockDim.x + threadIdx.x;
    if (t < CC) {
        float ty = -theta[2 * t];
        float tx = -theta[2 * t + 1];
        float fy = floorf(ty), fx = floorf(tx);
        float dy = ty - fy, dx = tx - fx;
        float wd = wdw[t];
        g_PI[t] = make_int2((int)fy, (int)fx);
        g_PW[t] = make_float4((1.0f - dy) * (1.0f - dx) * wd,
                              (1.0f - dy) * dx * wd,
                              dy * (1.0f - dx) * wd,
                              dy * dx * wd);
    }
    if (t < OO * CC / 4) {                 // 4096 float4 chunks
        int o = t >> 5;
        int c4 = (t & 31) << 2;
        float4 v = ((const float4*)wpw)[t];
        int p0 = pairpos(c4 >> 1);
        g_Bw[o * 64 + p0]     = packh2(v.x, v.y);
        g_Bw[o * 64 + p0 + 2] = packh2(v.z, v.w);
    }
}

// ---------------- gather: both subtiles, one pass ----------------
// LO0=true:  subtile0 (cols j0a+p)      needs low-edge column guards, subtile1 interior
// LO0=false: subtile1 (cols j0a+64+p)   needs high-edge column guards, subtile0 interior
template<bool LO0>
__device__ __forceinline__ void gather_both(
    const float* __restrict__ xb, uint32_t* __restrict__ Asw,
    const float4* __restrict__ SW, const int4* __restrict__ SO,
    int p, int cs, int j0a)
{
    const int jj = cs & 3;
    const int g0 = (cs >> 2) << 2;
    const int sg = ((p >> 2) & 7) << 1;
    const int jA = j0a + p;
    const int jB = jA + 64;
    uint32_t* A0 = Asw + p * RWRD;
    uint32_t* A1 = Asw + (64 + p) * RWRD;

    #pragma unroll
    for (int q = 0; q < 4; q++) {
        const int g = g0 + q;
        const int c00 = 16 * g + 2 * jj;
        float sA[4], sB[4];
        #pragma unroll
        for (int cc = 0; cc < 4; cc++) {
            int c = c00 + (cc & 1) + ((cc & 2) ? 8 : 0);
            int4 off = SO[c];
            float4 wv = SW[c];
            const float* b0 = xb + off.x;
            const float* b1 = xb + off.y;
            float a00, a01, a10, a11;
            float c00v, c01v, c10v, c11v;
            if (LO0) {
                int qq = jA + off.z;
                bool ok0 = qq >= 0, ok1 = qq >= -1;
                a00 = ok0 ? b0[jA] : 0.0f;  a01 = ok1 ? b0[jA + 1] : 0.0f;
                a10 = ok0 ? b1[jA] : 0.0f;  a11 = ok1 ? b1[jA + 1] : 0.0f;
                c00v = b0[jB]; c01v = b0[jB + 1]; c10v = b1[jB]; c11v = b1[jB + 1];
            } else {
                a00 = b0[jA]; a01 = b0[jA + 1]; a10 = b1[jA]; a11 = b1[jA + 1];
                int qq = jB + off.z;
                bool ok0 = qq <= 255, ok1 = qq <= 254;
                c00v = ok0 ? b0[jB] : 0.0f;  c01v = ok1 ? b0[jB + 1] : 0.0f;
                c10v = ok0 ? b1[jB] : 0.0f;  c11v = ok1 ? b1[jB + 1] : 0.0f;
            }
            sA[cc] = a00 * wv.x + a01 * wv.y + a10 * wv.z + a11 * wv.w;
            sB[cc] = c00v * wv.x + c01v * wv.y + c10v * wv.z + c11v * wv.w;
        }
        const int pos = (8 * g + 2 * jj) ^ sg;
        *(uint2*)(A0 + pos) = make_uint2(packh2(sA[0], sA[1]), packh2(sA[2], sA[3]));
        *(uint2*)(A1 + pos) = make_uint2(packh2(sB[0], sB[1]), packh2(sB[2], sB[3]));
    }
}

// ---------------- main kernel ----------------
__global__ void __launch_bounds__(NTHREADS, 2)
as2d_kernel(const float* __restrict__ x, float* __restrict__ out) {
    extern __shared__ char smem[];
    const int tid = threadIdx.x;
    const int wid = tid >> 5;
    const int lid = tid & 31;
    const int gid = lid >> 2;
    const int tig = lid & 3;

    // pair tiles: 512 pairs per batch (256 rows x 2 half-rows of 128 px = 2 subtiles)
    const int blk = blockIdx.x;
    const int b = blk >> 9;
    const int rem = blk & 511;
    const int row = rem >> 1;
    const int pairid = rem & 1;
    const int j0a = pairid << 7;

    uint32_t* Asw = (uint32_t*)(smem + SM_A);
    uint32_t* Bsw = (uint32_t*)(smem + SM_B);
    float4*   SW  = (float4*)(smem + SM_W);
    int4*     SO  = (int4*)(smem + SM_O);

    // ---- per-CTA setup: row validity folded into weights, c*HWSZ folded into offsets ----
    if (tid < CC) {
        int2 iv = g_PI[tid];
        float4 w = g_PW[tid];
        int r0 = row + iv.x;
        int r1 = r0 + 1;
        bool rok0 = (unsigned)r0 < (unsigned)HH;
        bool rok1 = (unsigned)r1 < (unsigned)HH;
        int cr0 = min(max(r0, 0), HH - 1);
        int cr1 = min(max(r1, 0), HH - 1);
        SW[tid] = make_float4(rok0 ? w.x : 0.0f, rok0 ? w.y : 0.0f,
                              rok1 ? w.z : 0.0f, rok1 ? w.w : 0.0f);
        SO[tid] = make_int4(tid * HWSZ + cr0 * WW + iv.y,
                            tid * HWSZ + cr1 * WW + iv.y, iv.y, 0);
    }
    // ---- stage B tile (once per pair) ----
    #pragma unroll
    for (int i = 0; i < 4; i++) {
        int w4 = tid + i * NTHREADS;
        int r = w4 >> 4;
        int pos = (w4 & 15) << 2;
        uint4 v = ((const uint4*)g_Bw)[w4];
        *(uint4*)(Bsw + r * RWRD + pos) = v;
    }
    __syncthreads();

    // ---- gather both subtiles ----
    {
        const int p = tid & 63;
        const int cs = tid >> 6;
        const float* xb = x + (size_t)b * CC * HWSZ;
        if (pairid == 0)
            gather_both<true>(xb, Asw, SW, SO, p, cs, j0a);
        else
            gather_both<false>(xb, Asw, SW, SO, p, cs, j0a);
    }
    __syncthreads();

    // ---- two subtile GEMMs + epilogues ----
    const int wm = wid & 3;
    const int wn = wid >> 2;
    #pragma unroll
    for (int t = 0; t < 2; t++) {
        float d[4][4] = {};
        {
            const uint32_t* At = Asw + t * 64 * RWRD;
            const int r1 = wm * 16 + gid;
            const int r2 = r1 + 8;
            const int sg1 = ((r1 >> 2) & 7) << 1;
            const int sg2 = ((r2 >> 2) & 7) << 1;
            const uint32_t* A1 = At + r1 * RWRD;
            const uint32_t* A2 = At + r2 * RWRD;
            const uint32_t* Bb = Bsw + (wn * 32 + gid) * RWRD + 2 * tig;
            #pragma unroll
            for (int k = 0; k < 8; k++) {
                int t2 = 8 * k + 2 * tig;
                uint2 aA = *(const uint2*)(A1 + (t2 ^ sg1));
                uint2 aB = *(const uint2*)(A2 + (t2 ^ sg2));
                #pragma unroll
                for (int nt = 0; nt < 4; nt++) {
                    uint2 bv = *(const uint2*)(Bb + nt * 8 * RWRD + 8 * k);
                    mma16(d[nt], aA.x, aB.x, aA.y, aB.y, bv.x, bv.y);
                }
            }
        }
        __syncthreads();   // all warps done reading A rows 0-63 (t=0) / E2 free (t=1)

        // ---- epilogue STS: fp16 pairs along o into E2 (= A rows 0-63 region) ----
        {
            const int pb = wm * 16 + gid;
            #pragma unroll
            for (int nt = 0; nt < 4; nt++) {
                int o2 = wn * 16 + nt * 4 + tig;     // o-pair index (o = 2*o2, 2*o2+1)
                Asw[o2 * RWRD + pb]     = packh2(d[nt][0], d[nt][1]);
                Asw[o2 * RWRD + pb + 8] = packh2(d[nt][2], d[nt][3]);
            }
        }
        __syncthreads();

        // ---- epilogue out: each thread expands one o-pair x 4 px -> 2 coalesced STG.128 ----
        {
            const int o2a = tid >> 4;
            const int l4 = tid & 15;
            float* obase = out + (size_t)b * OO * HWSZ + (size_t)row * WW + j0a + t * 64 + 4 * l4;
            #pragma unroll
            for (int s2 = 0; s2 < 2; s2++) {
                int o2 = o2a + s2 * 32;
                uint4 v4 = *(const uint4*)(Asw + o2 * RWRD + 4 * l4);
                float2 f0 = __half22float2(*(__half2*)&v4.x);
                float2 f1 = __half22float2(*(__half2*)&v4.y);
                float2 f2 = __half22float2(*(__half2*)&v4.z);
                float2 f3 = __half22float2(*(__half2*)&v4.w);
                *(float4*)(obase + (size_t)(2 * o2) * HWSZ) =
                    make_float4(f0.x, f1.x, f2.x, f3.x);
                *(float4*)(obase + (size_t)(2 * o2 + 1) * HWSZ) =
                    make_float4(f0.y, f1.y, f2.y, f3.y);
            }
        }
        // no sync needed: next mainloop reads A rows 64-127 / B only;
        // its post-mainloop sync orders E2 reuse against these reads.
    }
}

extern "C" void kernel_launch(void* const* d_in, const int* in_sizes, int n_in,
                              void* d_out, int out_size) {
    (void)in_sizes; (void)n_in; (void)out_size;
    const float* x     = (const float*)d_in[0];
    const float* theta = (const float*)d_in[1];
    const float* wdw   = (const float*)d_in[2];
    const float* wpw   = (const float*)d_in[3];
    float* out = (float*)d_out;

    prep_kernel<<<8, 512>>>(theta, wdw, wpw);
    cudaFuncSetAttribute(as2d_kernel, cudaFuncAttributeMaxDynamicSharedMemorySize, SM_TOTAL);
    as2d_kernel<<<BB * (HH * WW / 128), NTHREADS, SM_TOTAL>>>(x, out);
}